// round 15
// baseline (speedup 1.0000x reference)
#include <cuda_runtime.h>
#include <cuda_bf16.h>

#define NN     800
#define CC     64
#define TRS    40
#define SPT    10
#define BUF    120
#define TT     400
#define TT2    (TT + 2)
#define NBLK   100
#define RPB    8
#define THREADS 256
#define KPL    25
#define DCAP   64
#define HBYTES (BUF * NN * 2)
#define DT     1e-4f
#define GK     5.0f

// ---------------- static device scratch --------------------------------------
__device__ __align__(16) __nv_bfloat16 g_HT0[BUF * NN];            // transposed hE
__device__ __align__(16) float g_XTR[TRS * NN];                    // TR samples
__device__ __align__(16) unsigned long long g_G[(size_t)TT2 * NN]; // G[t+2][j]=(tag,x_j(t))
__device__ float g_rowsum[NN];
__device__ float g_rowsq[NN];
__device__ float g_invnorm;
__device__ int   g_flag64;

__device__ __forceinline__ unsigned long long ld_rlx64(const unsigned long long* p) {
    unsigned long long v;
    asm volatile("ld.relaxed.gpu.global.b64 %0, [%1];" : "=l"(v) : "l"(p) : "memory");
    return v;
}
__device__ __forceinline__ void st_rlx64(unsigned long long* p, unsigned long long v) {
    asm volatile("st.relaxed.gpu.global.b64 [%0], %1;" :: "l"(p), "l"(v) : "memory");
}
__device__ __forceinline__ float warp_sum(float v) {
    #pragma unroll
    for (int o = 16; o; o >>= 1) v += __shfl_xor_sync(0xffffffffu, v, o);
    return v;
}

// ---------------- per-row stats ----------------------------------------------
__global__ void k_rowstats(const float* __restrict__ sc) {
    int i = blockIdx.x, tid = threadIdx.x;
    float s1 = 0.f, s2 = 0.f;
    for (int j = tid; j < NN; j += 128) {
        float v = sc[i * NN + j];
        s1 += fabsf(v); s2 += v * v;
    }
    s1 = warp_sum(s1); s2 = warp_sum(s2);
    __shared__ float sh1[4], sh2[4];
    if ((tid & 31) == 0) { sh1[tid >> 5] = s1; sh2[tid >> 5] = s2; }
    __syncthreads();
    if (tid == 0) {
        g_rowsum[i] = sh1[0] + sh1[1] + sh1[2] + sh1[3];
        g_rowsq[i]  = sh2[0] + sh2[1] + sh2[2] + sh2[3];
    }
}

__global__ void k_norm() {
    int tid = threadIdx.x;
    float s = 0.f;
    for (int i = tid; i < NN; i += 256) s += g_rowsq[i];
    s = warp_sum(s);
    __shared__ float sh[8];
    if ((tid & 31) == 0) sh[tid >> 5] = s;
    __syncthreads();
    if (tid == 0) {
        float tot = 0.f;
        #pragma unroll
        for (int w = 0; w < 8; w++) tot += sh[w];
        g_invnorm = rsqrtf(tot);
    }
}

// ---------------- prep --------------------------------------------------------
__global__ void k_prep2(const float* __restrict__ hE, const void* __restrict__ delays) {
    int g = blockIdx.x * blockDim.x + threadIdx.x;
    if (g < BUF * NN) {
        int m = g / NN, j = g % NN;
        g_HT0[g] = __float2bfloat16(hE[j * BUF + (BUF - 1 - m)]);  // slot m = x(m-BUF)
    }
    if (g < NN) {
        g_G[g]      = (1ull << 32) | (unsigned long long)__float_as_uint(hE[g * BUF + 1]); // x(-2)
        g_G[NN + g] = (1ull << 32) | (unsigned long long)__float_as_uint(hE[g * BUF + 0]); // x(-1)
    } else if (g >= 2 * NN && g < TT2 * NN) {
        g_G[g] = 0ull;
    }
    if (g == 0) {
        const int* p = (const int*)delays;
        int any = 0;
        for (int k = 0; k < 100; k++) any |= p[2 * k + 1];
        g_flag64 = (any == 0) ? 1 : 0;
    }
}

// ---------------- main: pure tagged dataflow, deferred append -----------------
__global__ void __launch_bounds__(THREADS, 1)
k_main(const float* __restrict__ external, const float* __restrict__ hx,
       const float* __restrict__ sc, const float* __restrict__ noise,
       const void* __restrict__ delays) {
    extern __shared__ __align__(16) unsigned char smem_raw[];
    __nv_bfloat16* Hs = (__nv_bfloat16*)smem_raw;               // [BUF][NN]
    int*   j0_sh = (int*)(smem_raw + HBYTES);                   // [RPB*DCAP]
    float* w0_sh = (float*)(j0_sh + RPB * DCAP);
    int*   j1_sh = (int*)(w0_sh + RPB * DCAP);
    float* w1_sh = (float*)(j1_sh + RPB * DCAP);

    const int tid  = threadIdx.x;
    const int lane = tid & 31;
    const int wrp  = tid >> 5;
    const int i    = blockIdx.x * RPB + wrp;

    // stage full initial history into shared
    {
        const uint4* src = (const uint4*)g_HT0;
        uint4* dst = (uint4*)Hs;
        for (int idx = tid; idx < HBYTES / 16; idx += THREADS) dst[idx] = src[idx];
    }

    // step-invariant constants; ballot-compact d==0 / d==1; mask d<=1 in gather
    float wreg[KPL];
    int   dNN[KPL];
    int n0 = 0, n1 = 0;
    const int f64 = g_flag64;
    const int* dp = (const int*)delays;
    #pragma unroll
    for (int k = 0; k < KPL; k++) {
        int j = lane + 32 * k;
        int e = i * NN + j;
        float w = fabsf(sc[e]);
        int d = f64 ? dp[2 * e] : dp[e];
        unsigned b0 = __ballot_sync(0xffffffffu, d == 0);
        unsigned b1 = __ballot_sync(0xffffffffu, d == 1);
        if (d == 0) {
            int pos = n0 + __popc(b0 & ((1u << lane) - 1));
            if (pos < DCAP) { j0_sh[wrp * DCAP + pos] = j; w0_sh[wrp * DCAP + pos] = w; }
        }
        if (d == 1) {
            int pos = n1 + __popc(b1 & ((1u << lane) - 1));
            if (pos < DCAP) { j1_sh[wrp * DCAP + pos] = j; w1_sh[wrp * DCAP + pos] = w; }
        }
        if (d <= 1) { wreg[k] = 0.f; dNN[k] = NN; }   // masked; redirect is finite data
        else        { wreg[k] = w;  dNN[k] = d * NN; }
        n0 += __popc(b0); n1 += __popc(b1);
    }
    __syncwarp();
    int   j0r = 0, j1r = 0;
    float w0r = 0.f, w1r = 0.f;
    if (lane < n0 && lane < DCAP) { j0r = j0_sh[wrp * DCAP + lane]; w0r = w0_sh[wrp * DCAP + lane]; }
    if (lane < n1 && lane < DCAP) { j1r = j1_sh[wrp * DCAP + lane]; w1r = w1_sh[wrp * DCAP + lane]; }
    __syncthreads();

    const float Gn  = 500.0f * g_invnorm;
    const float grs = Gn * g_rowsum[i];
    float x = hx[2 * i], y = hx[2 * i + 1];

    // prologue: pre for step 0 = d>=2 (base slot(-1)) + d1 from Hs slot(-2)
    float u = __ldg(&external[i * (SPT * TRS) + 0]);
    float2 ns = *(const float2*)&noise[0 + 2 * i];
    float pre;
    {
        const int baseN = (BUF - 1) * NN;
        float a0 = 0.f, a1 = 0.f;
        #pragma unroll
        for (int k = 0; k < KPL; k++) {
            int sN = baseN - dNN[k];
            if (sN < 0) sN += BUF * NN;
            float h = __bfloat162float(Hs[sN + lane + 32 * k]);
            if (k & 1) a1 = fmaf(wreg[k], h, a1);
            else       a0 = fmaf(wreg[k], h, a0);
        }
        float acc = a0 + a1;
        if (lane < n1) acc = fmaf(w1r, __bfloat162float(Hs[(BUF - 2) * NN + j1r]), acc);
        for (int m = 32 + lane; m < n1; m += 32)
            acc = fmaf(w1_sh[wrp * DCAP + m],
                       __bfloat162float(Hs[(BUF - 2) * NN + j1_sh[wrp * DCAP + m]]), acc);
        pre = warp_sum(acc);
    }

    const bool bulk = (tid < NN / 4);
    unsigned long long a0c = 0, a1c = 0, a2c = 0, a3c = 0;   // carried bulk x(t-1)
    const unsigned long long* d0p = 0;
    unsigned long long d0v = 0ull;

    for (int t = 0; t < TT; t++) {
        // ========== CHAIN: d0 fold -> reduce -> update -> publish ==========
        float c0 = 0.f;
        if (t == 0) {
            const int baseN = (BUF - 1) * NN;
            if (lane < n0) c0 = w0r * __bfloat162float(Hs[baseN + j0r]);
            for (int m = 32 + lane; m < n0; m += 32)
                c0 = fmaf(w0_sh[wrp * DCAP + m],
                          __bfloat162float(Hs[baseN + j0_sh[wrp * DCAP + m]]), c0);
        } else {
            if (lane < n0) {
                while (!(d0v >> 32)) d0v = ld_rlx64(d0p);
                c0 = w0r * __uint_as_float((unsigned)d0v);
            }
            for (int m = 32 + lane; m < n0; m += 32) {   // astronomically rare
                const unsigned long long* p = g_G + (size_t)(t + 1) * NN + j0_sh[wrp * DCAP + m];
                unsigned long long v = ld_rlx64(p);
                while (!(v >> 32)) v = ld_rlx64(p);
                c0 = fmaf(w0_sh[wrp * DCAP + m], __uint_as_float((unsigned)v), c0);
            }
        }
        c0 = warp_sum(c0);

        float LEd = pre + c0;
        float r2 = x * x + y * y;
        float dx = (-0.5f - r2) * x - 10.0f * y + Gn * LEd - grs * x + GK * u;
        float dy = (-0.5f - r2) * y + 10.0f * x;
        float xn = x + DT * dx + ns.x;
        if (lane == 0) {
            st_rlx64(&g_G[(size_t)(t + 2) * NN + i],
                     (1ull << 32) | (unsigned long long)__float_as_uint(xn));
            if (t % SPT == SPT - 1) g_XTR[(t / SPT) * NN + i] = xn;
        }
        x = xn;
        y = y + DT * dy + ns.y;

        // ========== TAIL: deferred append + issue loads + pregather =========
        if (t + 1 < TT) {
            // STS carried x(t-1) (loaded last tail) into slot(t-1); verify tags
            if (t >= 1 && bulk) {
                const unsigned long long* src = g_G + (size_t)(t + 1) * NN + tid * 4;
                while (!(a0c >> 32)) a0c = ld_rlx64(src + 0);   // ~never taken
                while (!(a1c >> 32)) a1c = ld_rlx64(src + 1);
                while (!(a2c >> 32)) a2c = ld_rlx64(src + 2);
                while (!(a3c >> 32)) a3c = ld_rlx64(src + 3);
                __nv_bfloat162 p0 = __floats2bfloat162_rn(__uint_as_float((unsigned)a0c),
                                                          __uint_as_float((unsigned)a1c));
                __nv_bfloat162 p1 = __floats2bfloat162_rn(__uint_as_float((unsigned)a2c),
                                                          __uint_as_float((unsigned)a3c));
                uint2 pk; pk.x = *(unsigned*)&p0; pk.y = *(unsigned*)&p1;
                ((uint2*)(Hs + ((t - 1 + BUF) % BUF) * NN))[tid] = pk;
            }
            __syncthreads();   // slot(t-1) visible before next tail's pregather;
                               // slot(t-2) (stored last tail) visible for THIS pregather

            // issue: bulk x(t)=G[t+2] (unverified; checked next tail), d1 x(t-1),
            // speculative d0 x(t), u/ns — all overlap the pregather below
            if (bulk) {
                const unsigned long long* src = g_G + (size_t)(t + 2) * NN + tid * 4;
                a0c = ld_rlx64(src + 0);
                a1c = ld_rlx64(src + 1);
                a2c = ld_rlx64(src + 2);
                a3c = ld_rlx64(src + 3);
            }
            float d1f = 0.f;
            if (lane < n1) {
                const unsigned long long* p = g_G + (size_t)(t + 1) * NN + j1r;
                unsigned long long v = ld_rlx64(p);
                while (!(v >> 32)) v = ld_rlx64(p);   // one period stale: hits
                d1f = __uint_as_float((unsigned)v);
            }
            d0p = g_G + (size_t)(t + 2) * NN + j0r;
            d0v = 0ull;
            int tn = t + 1;
            u  = __ldg(&external[i * (SPT * TRS) + (tn % SPT) * TRS + (tn / SPT)]);
            ns = *(const float2*)&noise[(size_t)tn * 2 * NN + 2 * i];

            // pregather d>=2 for step t+1 (base slot(t); reads slots <= t-2 ✓)
            const int baseN = (t % BUF) * NN;
            float g0 = 0.f, g1 = 0.f;
            #pragma unroll
            for (int k = 0; k < KPL; k++) {
                int sN = baseN - dNN[k];
                if (sN < 0) sN += BUF * NN;
                float h = __bfloat162float(Hs[sN + lane + 32 * k]);
                if (k & 1) g1 = fmaf(wreg[k], h, g1);
                else       g0 = fmaf(wreg[k], h, g0);
            }
            float acc = g0 + g1;
            acc = fmaf(w1r, d1f, acc);
            for (int m = 32 + lane; m < n1; m += 32) {   // astronomically rare
                const unsigned long long* p = g_G + (size_t)(t + 1) * NN + j1_sh[wrp * DCAP + m];
                unsigned long long v = ld_rlx64(p);
                while (!(v >> 32)) v = ld_rlx64(p);
                acc = fmaf(w1_sh[wrp * DCAP + m], __uint_as_float((unsigned)v), acc);
            }
            pre = warp_sum(acc);

            // speculative first d0 read (late issue: high hit probability)
            if (lane < n0) d0v = ld_rlx64(d0p);
        }
    }
}

// ---------------- EEG projection ----------------------------------------------
__global__ void k_eeg(const float* __restrict__ lm, float* __restrict__ out) {
    int c = blockIdx.x, tr = blockIdx.y, tid = threadIdx.x;
    float s = 0.f;
    for (int i = tid; i < NN; i += 128)
        s += g_XTR[tr * NN + i] * lm[c * NN + i];
    s = warp_sum(s);
    __shared__ float sh[4];
    if ((tid & 31) == 0) sh[tid >> 5] = s;
    __syncthreads();
    if (tid == 0) out[c * TRS + tr] = 5.0f * (sh[0] + sh[1] + sh[2] + sh[3]) - 2.0f;
}

extern "C" void kernel_launch(void* const* d_in, const int* in_sizes, int n_in,
                              void* d_out, int out_size) {
    const float* external = (const float*)d_in[0];
    const float* hx       = (const float*)d_in[1];
    const float* hE       = (const float*)d_in[2];
    const float* sc       = (const float*)d_in[3];
    const float* lm       = (const float*)d_in[4];
    const float* noise    = (const float*)d_in[5];
    const void*  delays   = d_in[6];

    const int smem = HBYTES + 4 * RPB * DCAP * 4;
    cudaFuncSetAttribute(k_main, cudaFuncAttributeMaxDynamicSharedMemorySize, smem);

    k_rowstats<<<NN, 128>>>(sc);
    k_prep2<<<(TT2 * NN + 255) / 256, 256>>>(hE, delays);
    k_norm<<<1, 256>>>();
    k_main<<<NBLK, THREADS, smem>>>(external, hx, sc, noise, delays);
    k_eeg<<<dim3(CC, TRS), 128>>>(lm, (float*)d_out);
}

// round 16
// speedup vs baseline: 2.6842x; 2.6842x over previous
#include <cuda_runtime.h>
#include <cuda_bf16.h>

#define NN     800
#define CC     64
#define TRS    40
#define SPT    10
#define BUF    120
#define TT     400
#define TT2    (TT + 2)
#define NBLK   100
#define RPB    8
#define THREADS 288          // 8 compute warps + 1 sync warp
#define KPL    25
#define D0CAP  64
#define HBYTES (BUF * NN * 2)
#define DT     1e-4f
#define GK     5.0f

// ---------------- static device scratch --------------------------------------
__device__ __align__(16) __nv_bfloat16 g_HT0[BUF * NN];            // transposed hE
__device__ __align__(16) float g_XTR[TRS * NN];                    // TR samples
__device__ __align__(16) unsigned long long g_G[(size_t)TT2 * NN]; // G[t+2][j]=(tag,x_j(t))
__device__ int   g_ctr[TT];
__device__ float g_rowsum[NN];
__device__ float g_rowsq[NN];
__device__ float g_invnorm;
__device__ int   g_flag64;

__device__ __forceinline__ unsigned long long ld_rlx64(const unsigned long long* p) {
    unsigned long long v;
    asm volatile("ld.relaxed.gpu.global.b64 %0, [%1];" : "=l"(v) : "l"(p) : "memory");
    return v;
}
__device__ __forceinline__ void st_rlx64(unsigned long long* p, unsigned long long v) {
    asm volatile("st.relaxed.gpu.global.b64 [%0], %1;" :: "l"(p), "l"(v) : "memory");
}
__device__ __forceinline__ int ld_acq(const int* p) {
    int v;
    asm volatile("ld.global.acquire.gpu.s32 %0, [%1];" : "=r"(v) : "l"(p) : "memory");
    return v;
}
__device__ __forceinline__ void red_release(int* p) {
    asm volatile("red.release.gpu.global.add.s32 [%0], 1;" :: "l"(p) : "memory");
}
__device__ __forceinline__ float warp_sum(float v) {
    #pragma unroll
    for (int o = 16; o; o >>= 1) v += __shfl_xor_sync(0xffffffffu, v, o);
    return v;
}

// ---------------- per-row stats ----------------------------------------------
__global__ void k_rowstats(const float* __restrict__ sc) {
    int i = blockIdx.x, tid = threadIdx.x;
    float s1 = 0.f, s2 = 0.f;
    for (int j = tid; j < NN; j += 128) {
        float v = sc[i * NN + j];
        s1 += fabsf(v); s2 += v * v;
    }
    s1 = warp_sum(s1); s2 = warp_sum(s2);
    __shared__ float sh1[4], sh2[4];
    if ((tid & 31) == 0) { sh1[tid >> 5] = s1; sh2[tid >> 5] = s2; }
    __syncthreads();
    if (tid == 0) {
        g_rowsum[i] = sh1[0] + sh1[1] + sh1[2] + sh1[3];
        g_rowsq[i]  = sh2[0] + sh2[1] + sh2[2] + sh2[3];
    }
}

__global__ void k_norm() {
    int tid = threadIdx.x;
    float s = 0.f;
    for (int i = tid; i < NN; i += 256) s += g_rowsq[i];
    s = warp_sum(s);
    __shared__ float sh[8];
    if ((tid & 31) == 0) sh[tid >> 5] = s;
    __syncthreads();
    if (tid == 0) {
        float tot = 0.f;
        #pragma unroll
        for (int w = 0; w < 8; w++) tot += sh[w];
        g_invnorm = rsqrtf(tot);
    }
}

// ---------------- prep --------------------------------------------------------
__global__ void k_prep2(const float* __restrict__ hE, const void* __restrict__ delays) {
    int g = blockIdx.x * blockDim.x + threadIdx.x;
    if (g < BUF * NN) {
        int m = g / NN, j = g % NN;
        g_HT0[g] = __float2bfloat16(hE[j * BUF + (BUF - 1 - m)]);  // slot m = x(m-BUF)
    }
    if (g < NN) {
        g_G[g]      = (1ull << 32) | (unsigned long long)__float_as_uint(hE[g * BUF + 1]); // x(-2)
        g_G[NN + g] = (1ull << 32) | (unsigned long long)__float_as_uint(hE[g * BUF + 0]); // x(-1)
    } else if (g >= 2 * NN && g < TT2 * NN) {
        g_G[g] = 0ull;
    }
    if (g < TT) g_ctr[g] = 0;
    if (g == 0) {
        const int* p = (const int*)delays;
        int any = 0;
        for (int k = 0; k < 100; k++) any |= p[2 * k + 1];
        g_flag64 = (any == 0) ? 1 : 0;
    }
}

// ---------------- main: R11 + dedicated sync warp -----------------------------
__global__ void __launch_bounds__(THREADS, 1)
k_main(const float* __restrict__ external, const float* __restrict__ hx,
       const float* __restrict__ sc, const float* __restrict__ noise,
       const void* __restrict__ delays) {
    extern __shared__ __align__(16) unsigned char smem_raw[];
    __nv_bfloat16* Hs = (__nv_bfloat16*)smem_raw;               // [BUF][NN]
    int*   j0_sh = (int*)(smem_raw + HBYTES);                   // [RPB*D0CAP]
    float* w0_sh = (float*)(j0_sh + RPB * D0CAP);               // [RPB*D0CAP]

    const int tid  = threadIdx.x;
    const int lane = tid & 31;
    const int wrp  = tid >> 5;                 // 0..8
    const bool cw  = (wrp < RPB);              // compute warp?
    const int i    = blockIdx.x * RPB + (cw ? wrp : 0);

    // stage full initial history into shared (all 9 warps help)
    {
        const uint4* src = (const uint4*)g_HT0;
        uint4* dst = (uint4*)Hs;
        for (int idx = tid; idx < HBYTES / 16; idx += THREADS) dst[idx] = src[idx];
    }

    // step-invariant constants; ballot-compact d==0 list; mask d0 in gather
    float wreg[KPL];
    int   dNN[KPL];
    int n0 = 0;
    int   j0r = 0; float w0r = 0.f;
    const int f64 = g_flag64;
    const int* dp = (const int*)delays;
    if (cw) {
        #pragma unroll
        for (int k = 0; k < KPL; k++) {
            int j = lane + 32 * k;
            int e = i * NN + j;
            float w = fabsf(sc[e]);
            int d = f64 ? dp[2 * e] : dp[e];
            unsigned b0 = __ballot_sync(0xffffffffu, d == 0);
            if (d == 0) {
                int pos = n0 + __popc(b0 & ((1u << lane) - 1));
                if (pos < D0CAP) { j0_sh[wrp * D0CAP + pos] = j; w0_sh[wrp * D0CAP + pos] = w; }
                wreg[k] = 0.f;
                dNN[k]  = NN;                 // redirect to valid slot (weight 0)
            } else {
                wreg[k] = w;
                dNN[k]  = d * NN;
            }
            n0 += __popc(b0);
        }
        __syncwarp();
        if (lane < n0 && lane < D0CAP) { j0r = j0_sh[wrp * D0CAP + lane]; w0r = w0_sh[wrp * D0CAP + lane]; }
    }
    __syncthreads();

    const float Gn  = 500.0f * g_invnorm;
    const float grs = cw ? (Gn * g_rowsum[i]) : 0.f;
    float x = cw ? hx[2 * i] : 0.f;
    float y = cw ? hx[2 * i + 1] : 0.f;

    // prologue (compute warps): pre for step 0 + inputs for step 0
    float u = 0.f;
    float2 ns = make_float2(0.f, 0.f);
    float pre = 0.f;
    if (cw) {
        u  = __ldg(&external[i * (SPT * TRS) + 0]);
        ns = *(const float2*)&noise[0 + 2 * i];
        const int baseN = (BUF - 1) * NN;
        float a0 = 0.f, a1 = 0.f;
        #pragma unroll
        for (int k = 0; k < KPL; k++) {
            int sN = baseN - dNN[k];
            if (sN < 0) sN += BUF * NN;
            float h = __bfloat162float(Hs[sN + lane + 32 * k]);
            if (k & 1) a1 = fmaf(wreg[k], h, a1);
            else       a0 = fmaf(wreg[k], h, a0);
        }
        pre = warp_sum(a0 + a1);
    }
    const unsigned long long* d0p = 0;   // carried speculative d0 pointer/value
    unsigned long long d0v = 0ull;

    for (int t = 0; t < TT; t++) {
        // ========== CHAIN (compute warps): d0 fold -> reduce -> update -> publish
        if (cw) {
            float c0 = 0.f;
            if (t == 0) {
                const int baseN = (BUF - 1) * NN;
                if (lane < n0) c0 = w0r * __bfloat162float(Hs[baseN + j0r]);
                for (int m = 32 + lane; m < n0; m += 32)
                    c0 = fmaf(w0_sh[wrp * D0CAP + m],
                              __bfloat162float(Hs[baseN + j0_sh[wrp * D0CAP + m]]), c0);
            } else {
                if (lane < n0) {
                    while (!(d0v >> 32)) d0v = ld_rlx64(d0p);
                    c0 = w0r * __uint_as_float((unsigned)d0v);
                }
                for (int m = 32 + lane; m < n0; m += 32) {   // astronomically rare
                    const unsigned long long* p = g_G + (size_t)(t + 1) * NN + j0_sh[wrp * D0CAP + m];
                    unsigned long long v = ld_rlx64(p);
                    while (!(v >> 32)) v = ld_rlx64(p);
                    c0 = fmaf(w0_sh[wrp * D0CAP + m], __uint_as_float((unsigned)v), c0);
                }
            }
            c0 = warp_sum(c0);

            float LEd = pre + c0;
            float r2 = x * x + y * y;
            float dx = (-0.5f - r2) * x - 10.0f * y + Gn * LEd - grs * x + GK * u;
            float dy = (-0.5f - r2) * y + 10.0f * x;
            float xn = x + DT * dx + ns.x;
            if (lane == 0) {
                st_rlx64(&g_G[(size_t)(t + 2) * NN + i],
                         (1ull << 32) | (unsigned long long)__float_as_uint(xn));
                if (t % SPT == SPT - 1) g_XTR[(t / SPT) * NN + i] = xn;
            }
            x = xn;
            y = y + DT * dy + ns.y;
        } else {
            // sync warp: pre-resolve the guard during the others' chain
            if (lane == 0 && t >= 1 && t + 1 < TT)
                while (ld_acq(&g_ctr[t - 1]) < NBLK) { }
        }

        // ========== TAIL: prepare step t+1 (structure identical to R11) =======
        if (t + 1 < TT) {
            __syncthreads();                 // guard satisfied; publishes done

            // bulk one-shot load of x(t-1) = G[t+1]; append into slot(t-1)
            const bool dob = (tid < NN / 4);
            if (dob) {
                const ulonglong2* src = (const ulonglong2*)(g_G + (size_t)(t + 1) * NN) + tid * 2;
                ulonglong2 q0 = __ldcg(src);
                ulonglong2 q1 = __ldcg(src + 1);
                __nv_bfloat162 p0 = __floats2bfloat162_rn(__uint_as_float((unsigned)q0.x),
                                                          __uint_as_float((unsigned)q0.y));
                __nv_bfloat162 p1 = __floats2bfloat162_rn(__uint_as_float((unsigned)q1.x),
                                                          __uint_as_float((unsigned)q1.y));
                uint2 pk; pk.x = *(unsigned*)&p0; pk.y = *(unsigned*)&p1;
                ((uint2*)(Hs + ((t - 1 + BUF) % BUF) * NN))[tid] = pk;
            }
            __syncthreads();   // appends visible
            if (wrp == RPB && lane == 0) red_release(&g_ctr[t]);  // R11 release point

            if (cw) {
                // pre-gather ALL d>=1 terms for step t+1 (base = slot(t))
                const int baseN = (t % BUF) * NN;
                float a0 = 0.f, a1 = 0.f;
                #pragma unroll
                for (int k = 0; k < KPL; k++) {
                    int sN = baseN - dNN[k];
                    if (sN < 0) sN += BUF * NN;
                    float h = __bfloat162float(Hs[sN + lane + 32 * k]);
                    if (k & 1) a1 = fmaf(wreg[k], h, a1);
                    else       a0 = fmaf(wreg[k], h, a0);
                }
                pre = warp_sum(a0 + a1);

                // prefetch inputs + speculative first d0 load for step t+1
                int tn = t + 1;
                u  = __ldg(&external[i * (SPT * TRS) + (tn % SPT) * TRS + (tn / SPT)]);
                ns = *(const float2*)&noise[(size_t)tn * 2 * NN + 2 * i];
                d0p = g_G + (size_t)(t + 2) * NN + j0r;
                d0v = 0ull;
                if (lane < n0) d0v = ld_rlx64(d0p);
            }
        }
    }
}

// ---------------- EEG projection ----------------------------------------------
__global__ void k_eeg(const float* __restrict__ lm, float* __restrict__ out) {
    int c = blockIdx.x, tr = blockIdx.y, tid = threadIdx.x;
    float s = 0.f;
    for (int i = tid; i < NN; i += 128)
        s += g_XTR[tr * NN + i] * lm[c * NN + i];
    s = warp_sum(s);
    __shared__ float sh[4];
    if ((tid & 31) == 0) sh[tid >> 5] = s;
    __syncthreads();
    if (tid == 0) out[c * TRS + tr] = 5.0f * (sh[0] + sh[1] + sh[2] + sh[3]) - 2.0f;
}

extern "C" void kernel_launch(void* const* d_in, const int* in_sizes, int n_in,
                              void* d_out, int out_size) {
    const float* external = (const float*)d_in[0];
    const float* hx       = (const float*)d_in[1];
    const float* hE       = (const float*)d_in[2];
    const float* sc       = (const float*)d_in[3];
    const float* lm       = (const float*)d_in[4];
    const float* noise    = (const float*)d_in[5];
    const void*  delays   = d_in[6];

    const int smem = HBYTES + RPB * D0CAP * 8;
    cudaFuncSetAttribute(k_main, cudaFuncAttributeMaxDynamicSharedMemorySize, smem);

    k_rowstats<<<NN, 128>>>(sc);
    k_prep2<<<(TT2 * NN + 255) / 256, 256>>>(hE, delays);
    k_norm<<<1, 256>>>();
    k_main<<<NBLK, THREADS, smem>>>(external, hx, sc, noise, delays);
    k_eeg<<<dim3(CC, TRS), 128>>>(lm, (float*)d_out);
}